// round 8
// baseline (speedup 1.0000x reference)
#include <cuda_runtime.h>
#include <stdint.h>
#include <math.h>

#define BQ 2
#define CH 256
#define HH 96
#define WW 96
#define HW (HH*WW)          // 9216
#define NPOS (BQ*HW)        // 18432
#define KDIM 2304           // 9 * 256
#define LAYERS 4
#define TAPN (64*9)
#define KSPLIT 4

typedef unsigned long long ull;
typedef unsigned int u32;

// ---- scratch (static device globals: allocation-free) ----
__device__ float g_x0[NPOS*CH];            // ping  (NHWC)
__device__ float g_x1[NPOS*CH];            // pong  (NHWC)
__device__ float g_offp[KSPLIT][NPOS*18];  // offset partials (split-K)
__device__ float g_dwr[LAYERS*KDIM*CH];    // deform weights [l][k*256+c][o]
__device__ float g_owr[LAYERS*KDIM*18];    // offset weights [l][k*256+c][oc]

// ---------------- layout transforms ----------------
__global__ void k_nchw2nhwc(const float* __restrict__ x) {
    int idx = blockIdx.x*256 + threadIdx.x;        // NHWC linear
    if (idx >= NPOS*CH) return;
    int c   = idx & 255;
    int pos = idx >> 8;
    int b   = pos / HW;
    int hw  = pos - b*HW;
    g_x0[idx] = x[(b*CH + c)*HW + hw];
}

__global__ void k_nhwc2nchw(float* __restrict__ o) {
    int idx = blockIdx.x*256 + threadIdx.x;        // NCHW linear
    if (idx >= NPOS*CH) return;
    int hw = idx % HW;
    int bc = idx / HW;
    int c  = bc % CH;
    int b  = bc / CH;
    o[idx] = g_x0[(b*HW + hw)*CH + c];
}

__global__ void k_wtrans_dw(const float* __restrict__ dw) {
    int idx = blockIdx.x*256 + threadIdx.x;
    if (idx >= LAYERS*KDIM*CH) return;
    int o = idx & 255;
    int r = idx >> 8;            // l*KDIM + j
    int j = r % KDIM;
    int l = r / KDIM;
    int k = j >> 8;
    int c = j & 255;
    g_dwr[idx] = dw[((l*CH + o)*CH + c)*9 + k];
}

__global__ void k_wtrans_ow(const float* __restrict__ ow) {
    int idx = blockIdx.x*256 + threadIdx.x;
    if (idx >= LAYERS*KDIM*18) return;
    int o = idx % 18;
    int r = idx / 18;
    int j = r % KDIM;
    int l = r / KDIM;
    int k = j >> 8;
    int c = j & 255;
    g_owr[idx] = ow[((l*18 + o)*CH + c)*9 + k];
}

// ---------------- offset conv: M=18432, N=18, K=2304, split-K x4 ----------------
__global__ void __launch_bounds__(256) k_offconv(int flag, int l,
                                                 const float* __restrict__ ob_all) {
    const float* xin = flag ? g_x1 : g_x0;
    const float* wr  = g_owr + l*KDIM*18;
    const float* ob  = ob_all + l*18;
    int z = blockIdx.y;

    __shared__ float Ash[32*65];
    __shared__ float Bsh[32*18];
    __shared__ int   sBase[64];
    __shared__ short sH[64], sW[64];

    int t = threadIdx.x;
    int pos0 = blockIdx.x * 64;
    if (t < 64) {
        int gp = pos0 + t;
        int b  = gp / HW;
        int hw = gp - b*HW;
        int h  = hw / WW;
        sBase[t] = b*HW;
        sH[t] = (short)h;
        sW[t] = (short)(hw - h*WW);
    }
    __syncthreads();

    int p  = t & 63;
    int g  = t >> 6;         // 0..3
    int cc = t & 31;
    int grp = t >> 5;        // 0..7

    float acc[5] = {0.f,0.f,0.f,0.f,0.f};

    int kc0 = z * 18;
    for (int kc = kc0; kc < kc0 + 18; kc++) {
        int k  = kc >> 3;
        int c0 = (kc & 7) << 5;
        int ky = k/3 - 1, kx = k - (k/3)*3 - 1;

        for (int i = t; i < 32*18; i += 256) {
            int rr = i / 18; int oo = i - rr*18;
            Bsh[i] = wr[(k*CH + c0 + rr)*18 + oo];
        }
        #pragma unroll
        for (int i = 0; i < 8; i++) {
            int pp = grp*8 + i;
            int yy = (int)sH[pp] + ky;
            int xx = (int)sW[pp] + kx;
            float v = 0.f;
            if (yy >= 0 && yy < HH && xx >= 0 && xx < WW)
                v = xin[(sBase[pp] + yy*WW + xx)*CH + c0 + cc];
            Ash[cc*65 + pp] = v;
        }
        __syncthreads();
        #pragma unroll
        for (int kk2 = 0; kk2 < 32; kk2++) {
            float a = Ash[kk2*65 + p];
            #pragma unroll
            for (int q = 0; q < 5; q++) {
                int o = g + 4*q;
                if (o < 18) acc[q] += a * Bsh[kk2*18 + o];
            }
        }
        __syncthreads();
    }
    int gp = pos0 + p;
    #pragma unroll
    for (int q = 0; q < 5; q++) {
        int o = g + 4*q;
        if (o < 18) g_offp[z][gp*18 + o] = acc[q] + (z == 0 ? ob[o] : 0.f);
    }
}

// ---------------- deformable conv implicit GEMM (FFMA2 / f32x2) ----------------
// BM=64 positions, BN=256 outputs, K-chunks of 32; 256 threads, 8x8 reg tiles.
// A tile stored DUPLICATED ((a,a) pairs) so ld.shared.v2.b64 feeds fma.rn.f32x2.
#define ASTRIDE 132                       // floats per duplicated A row (16B aligned)
#define DSM_A    0
#define DSM_B    (32*ASTRIDE)             // 4224
#define DSM_TW   (DSM_B + 32*256)         // 12416
#define DSM_TI   (DSM_TW + TAPN*4)        // 14720
#define DSM_FLOATS (DSM_TI + TAPN*4)      // 17024
#define DSM_BYTES  (DSM_FLOATS*4)         // 68096

#define FMA_F32X2(d, a, b) \
    asm volatile("fma.rn.f32x2 %0, %1, %2, %0;" : "+l"(d) : "l"(a), "l"(b))

__global__ void __launch_bounds__(256,2) k_deform(int flag, int l,
                                                  const float* __restrict__ db_all) {
    const float* xin  = flag ? g_x1 : g_x0;
    float*       yout = flag ? g_x0 : g_x1;
    const float* wr   = g_dwr + l*KDIM*CH;
    const float* bias = db_all + l*CH;

    extern __shared__ float smem[];
    float* Ash  = smem + DSM_A;
    float* Bsh  = smem + DSM_B;
    float* tw   = smem + DSM_TW;
    int*   tidx = (int*)(smem + DSM_TI);

    u32 sbase;
    asm("{ .reg .u64 t; cvta.to.shared.u64 t, %1; cvt.u32.u64 %0, t; }"
        : "=r"(sbase) : "l"(smem));
    u32 sA = sbase + DSM_A*4;
    u32 sB = sbase + DSM_B*4;

    int t = threadIdx.x;
    int pos0 = blockIdx.x * 64;

    // ---- precompute bilinear taps (offsets = sum of 4 split-K partials) ----
    for (int it = t; it < TAPN; it += 256) {
        int p = it / 9;
        int k = it - p*9;
        int gp = pos0 + p;
        int b  = gp / HW;
        int hw = gp - b*HW;
        int h  = hw / WW;
        int w  = hw - h*WW;
        int oi = gp*18 + 2*k;
        float oy = g_offp[0][oi]   + g_offp[1][oi]   + g_offp[2][oi]   + g_offp[3][oi];
        float ox = g_offp[0][oi+1] + g_offp[1][oi+1] + g_offp[2][oi+1] + g_offp[3][oi+1];
        float py = (float)(h - 1 + k/3) + oy;
        float px = (float)(w - 1 + (k - (k/3)*3)) + ox;
        float y0f = floorf(py), x0f = floorf(px);
        float fy = py - y0f,   fx = px - x0f;
        int y0 = (int)y0f, x0 = (int)x0f;
        float wy0 = 1.f - fy, wx0 = 1.f - fx;
        int base = b*HW;
        #pragma unroll
        for (int ti = 0; ti < 4; ti++) {
            int yi = y0 + (ti >> 1);
            int xi = x0 + (ti & 1);
            float wv = ((ti >> 1) ? fy : wy0) * ((ti & 1) ? fx : wx0);
            bool valid = (yi >= 0 && yi < HH && xi >= 0 && xi < WW);
            int yc = min(max(yi, 0), HH-1);
            int xc = min(max(xi, 0), WW-1);
            tw  [it*4 + ti] = valid ? wv : 0.f;
            tidx[it*4 + ti] = (base + yc*WW + xc) * CH;
        }
    }
    __syncthreads();

    ull acc2[8][4];
    #pragma unroll
    for (int i = 0; i < 8; i++)
        #pragma unroll
        for (int q = 0; q < 4; q++) acc2[i][q] = 0ull;

    int cc  = t & 31;
    int grp = t >> 5;            // 0..7
    int tm  = grp;               // row group (positions)
    int tn  = cc;                // col group (outputs)

    float4*       Bsh4 = (float4*)Bsh;
    const float4* wr4  = (const float4*)wr;

    int br = t >> 3, bq = t & 7;       // B-load mapping: 32 rows x 8 thr/row

    for (int kc = 0; kc < 72; kc++) {
        int k  = kc >> 3;
        int c0 = (kc & 7) << 5;
        int jbase = k*CH + c0;

        // B chunk: 32 rows x 256 floats = 64 float4/row; 8 thr/row x 8 f4 each
        #pragma unroll
        for (int ii = 0; ii < 8; ii++)
            Bsh4[br*64 + bq + ii*8] = wr4[(jbase + br)*64 + bq + ii*8];

        // A chunk: sample 64 pos x 32 channels, store duplicated (a,a)
        #pragma unroll
        for (int i = 0; i < 8; i++) {
            int pp = grp*8 + i;
            int tb = (pp*9 + k)*4;
            int c  = c0 + cc;
            float v = tw[tb  ] * xin[tidx[tb  ] + c]
                    + tw[tb+1] * xin[tidx[tb+1] + c]
                    + tw[tb+2] * xin[tidx[tb+2] + c]
                    + tw[tb+3] * xin[tidx[tb+3] + c];
            *(float2*)&Ash[cc*ASTRIDE + pp*2] = make_float2(v, v);
        }
        __syncthreads();

        #pragma unroll 4
        for (int kk2 = 0; kk2 < 32; kk2++) {
            ull aa[8], bb[4];
            u32 aaddr = sA + (u32)(kk2*ASTRIDE*4 + tm*64);
            asm volatile("ld.shared.v2.b64 {%0,%1}, [%2];"
                         : "=l"(aa[0]), "=l"(aa[1]) : "r"(aaddr));
            asm volatile("ld.shared.v2.b64 {%0,%1}, [%2];"
                         : "=l"(aa[2]), "=l"(aa[3]) : "r"(aaddr + 16));
            asm volatile("ld.shared.v2.b64 {%0,%1}, [%2];"
                         : "=l"(aa[4]), "=l"(aa[5]) : "r"(aaddr + 32));
            asm volatile("ld.shared.v2.b64 {%0,%1}, [%2];"
                         : "=l"(aa[6]), "=l"(aa[7]) : "r"(aaddr + 48));
            u32 baddr = sB + (u32)(kk2*1024 + tn*32);
            asm volatile("ld.shared.v2.b64 {%0,%1}, [%2];"
                         : "=l"(bb[0]), "=l"(bb[1]) : "r"(baddr));
            asm volatile("ld.shared.v2.b64 {%0,%1}, [%2];"
                         : "=l"(bb[2]), "=l"(bb[3]) : "r"(baddr + 16));
            #pragma unroll
            for (int i = 0; i < 8; i++) {
                FMA_F32X2(acc2[i][0], aa[i], bb[0]);
                FMA_F32X2(acc2[i][1], aa[i], bb[1]);
                FMA_F32X2(acc2[i][2], aa[i], bb[2]);
                FMA_F32X2(acc2[i][3], aa[i], bb[3]);
            }
        }
        __syncthreads();
    }

    // ---- epilogue: bias + relu, NHWC store ----
    float bb8[8];
    #pragma unroll
    for (int j = 0; j < 8; j++) bb8[j] = bias[tn*8 + j];
    #pragma unroll
    for (int i = 0; i < 8; i++) {
        int gp = pos0 + tm*8 + i;
        float o[8];
        #pragma unroll
        for (int q = 0; q < 4; q++) {
            float lo, hi;
            asm("mov.b64 {%0,%1}, %2;" : "=f"(lo), "=f"(hi) : "l"(acc2[i][q]));
            o[2*q]   = fmaxf(lo + bb8[2*q],   0.f);
            o[2*q+1] = fmaxf(hi + bb8[2*q+1], 0.f);
        }
        float4* dst = (float4*)(yout + gp*256 + tn*8);
        dst[0] = make_float4(o[0], o[1], o[2], o[3]);
        dst[1] = make_float4(o[4], o[5], o[6], o[7]);
    }
}

// ---------------- launch ----------------
extern "C" void kernel_launch(void* const* d_in, const int* in_sizes, int n_in,
                              void* d_out, int out_size) {
    const float* x     = (const float*)d_in[0];
    const float* off_w = (const float*)d_in[1];
    const float* off_b = (const float*)d_in[2];
    const float* dw    = (const float*)d_in[3];
    const float* db    = (const float*)d_in[4];
    float* out = (float*)d_out;

    cudaFuncSetAttribute(k_deform, cudaFuncAttributeMaxDynamicSharedMemorySize, DSM_BYTES);

    k_nchw2nhwc<<<(NPOS*CH + 255)/256, 256>>>(x);
    k_wtrans_dw<<<(LAYERS*KDIM*CH + 255)/256, 256>>>(dw);
    k_wtrans_ow<<<(LAYERS*KDIM*18 + 255)/256, 256>>>(off_w);

    dim3 og(NPOS/64, KSPLIT);
    for (int l = 0; l < LAYERS; l++) {
        int flag = l & 1;   // 0: in=g_x0 out=g_x1
        k_offconv<<<og, 256>>>(flag, l, off_b);
        k_deform <<<NPOS/64, 256, DSM_BYTES>>>(flag, l, db);
    }
    // after 4 layers result is in g_x0
    k_nhwc2nchw<<<(NPOS*CH + 255)/256, 256>>>(out);
}

// round 10
// speedup vs baseline: 1.1931x; 1.1931x over previous
#include <cuda_runtime.h>
#include <stdint.h>
#include <math.h>

#define BQ 2
#define CH 256
#define HH 96
#define WW 96
#define HW (HH*WW)          // 9216
#define NPOS (BQ*HW)        // 18432
#define KDIM 2304           // 9 * 256
#define LAYERS 4
#define TAPN (64*9)
#define KSPLIT 8

// ---- scratch (static device globals: allocation-free) ----
__device__ float g_x0[NPOS*CH];            // ping  (NHWC)
__device__ float g_x1[NPOS*CH];            // pong  (NHWC)
__device__ float g_offp[KSPLIT][NPOS*18];  // offset partials (split-K)
__device__ float g_dwr[LAYERS*KDIM*CH];    // deform weights [l][k*256+c][o]
__device__ float g_owr[LAYERS*KDIM*18];    // offset weights [l][k*256+c][oc]

// ---------------- layout transforms ----------------
__global__ void k_nchw2nhwc(const float* __restrict__ x) {
    int idx = blockIdx.x*256 + threadIdx.x;        // NHWC linear
    if (idx >= NPOS*CH) return;
    int c   = idx & 255;
    int pos = idx >> 8;
    int b   = pos / HW;
    int hw  = pos - b*HW;
    g_x0[idx] = x[(b*CH + c)*HW + hw];
}

__global__ void k_nhwc2nchw(float* __restrict__ o) {
    int idx = blockIdx.x*256 + threadIdx.x;        // NCHW linear
    if (idx >= NPOS*CH) return;
    int hw = idx % HW;
    int bc = idx / HW;
    int c  = bc % CH;
    int b  = bc / CH;
    o[idx] = g_x0[(b*HW + hw)*CH + c];
}

__global__ void k_wtrans_dw(const float* __restrict__ dw) {
    int idx = blockIdx.x*256 + threadIdx.x;
    if (idx >= LAYERS*KDIM*CH) return;
    int o = idx & 255;
    int r = idx >> 8;            // l*KDIM + j
    int j = r % KDIM;
    int l = r / KDIM;
    int k = j >> 8;
    int c = j & 255;
    g_dwr[idx] = dw[((l*CH + o)*CH + c)*9 + k];
}

__global__ void k_wtrans_ow(const float* __restrict__ ow) {
    int idx = blockIdx.x*256 + threadIdx.x;
    if (idx >= LAYERS*KDIM*18) return;
    int o = idx % 18;
    int r = idx / 18;
    int j = r % KDIM;
    int l = r / KDIM;
    int k = j >> 8;
    int c = j & 255;
    g_owr[idx] = ow[((l*18 + o)*CH + c)*9 + k];
}

// ---------------- offset conv: M=18432, N=18, K=2304, split-K x8 ----------------
__global__ void __launch_bounds__(256) k_offconv(int flag, int l,
                                                 const float* __restrict__ ob_all) {
    const float* xin = flag ? g_x1 : g_x0;
    const float* wr  = g_owr + l*KDIM*18;
    const float* ob  = ob_all + l*18;
    int z = blockIdx.y;

    __shared__ float Ash[32*65];
    __shared__ float Bsh[32*18];
    __shared__ int   sBase[64];
    __shared__ short sH[64], sW[64];

    int t = threadIdx.x;
    int pos0 = blockIdx.x * 64;
    if (t < 64) {
        int gp = pos0 + t;
        int b  = gp / HW;
        int hw = gp - b*HW;
        int h  = hw / WW;
        sBase[t] = b*HW;
        sH[t] = (short)h;
        sW[t] = (short)(hw - h*WW);
    }
    __syncthreads();

    int p  = t & 63;
    int g  = t >> 6;         // 0..3
    int cc = t & 31;
    int grp = t >> 5;        // 0..7

    float acc[5] = {0.f,0.f,0.f,0.f,0.f};

    int kc0 = z * 9;
    for (int kc = kc0; kc < kc0 + 9; kc++) {
        int k  = kc >> 3;
        int c0 = (kc & 7) << 5;
        int ky = k/3 - 1, kx = k - (k/3)*3 - 1;

        for (int i = t; i < 32*18; i += 256) {
            int rr = i / 18; int oo = i - rr*18;
            Bsh[i] = wr[(k*CH + c0 + rr)*18 + oo];
        }
        #pragma unroll
        for (int i = 0; i < 8; i++) {
            int pp = grp*8 + i;
            int yy = (int)sH[pp] + ky;
            int xx = (int)sW[pp] + kx;
            float v = 0.f;
            if (yy >= 0 && yy < HH && xx >= 0 && xx < WW)
                v = xin[(sBase[pp] + yy*WW + xx)*CH + c0 + cc];
            Ash[cc*65 + pp] = v;
        }
        __syncthreads();
        #pragma unroll
        for (int kk2 = 0; kk2 < 32; kk2++) {
            float a = Ash[kk2*65 + p];
            #pragma unroll
            for (int q = 0; q < 5; q++) {
                int o = g + 4*q;
                if (o < 18) acc[q] += a * Bsh[kk2*18 + o];
            }
        }
        __syncthreads();
    }
    int gp = pos0 + p;
    #pragma unroll
    for (int q = 0; q < 5; q++) {
        int o = g + 4*q;
        if (o < 18) g_offp[z][gp*18 + o] = acc[q] + (z == 0 ? ob[o] : 0.f);
    }
}

// ---------------- deformable conv implicit GEMM (scalar FFMA, proven) ----------------
// BM=64 positions, BN=256 outputs, K-chunks of 32; 256 threads, 8x8 reg tiles.
#define DSM_A    0
#define DSM_B    (32*65)
#define DSM_TW   (DSM_B + 32*256)
#define DSM_TI   (DSM_TW + TAPN*4)
#define DSM_FLOATS (DSM_TI + TAPN*4)
#define DSM_BYTES  (DSM_FLOATS*4)       // 59520

__global__ void __launch_bounds__(256,2) k_deform(int flag, int l,
                                                  const float* __restrict__ db_all) {
    const float* xin  = flag ? g_x1 : g_x0;
    float*       yout = flag ? g_x0 : g_x1;
    const float* wr   = g_dwr + l*KDIM*CH;
    const float* bias = db_all + l*CH;

    extern __shared__ float smem[];
    float* Ash  = smem + DSM_A;
    float* Bsh  = smem + DSM_B;
    float* tw   = smem + DSM_TW;
    int*   tidx = (int*)(smem + DSM_TI);

    int t = threadIdx.x;
    int pos0 = blockIdx.x * 64;

    // ---- precompute bilinear taps (offsets = sum of split-K partials) ----
    for (int it = t; it < TAPN; it += 256) {
        int p = it / 9;
        int k = it - p*9;
        int gp = pos0 + p;
        int b  = gp / HW;
        int hw = gp - b*HW;
        int h  = hw / WW;
        int w  = hw - h*WW;
        int oi = gp*18 + 2*k;
        float oy = 0.f, ox = 0.f;
        #pragma unroll
        for (int z = 0; z < KSPLIT; z++) {
            oy += g_offp[z][oi];
            ox += g_offp[z][oi+1];
        }
        float py = (float)(h - 1 + k/3) + oy;
        float px = (float)(w - 1 + (k - (k/3)*3)) + ox;
        float y0f = floorf(py), x0f = floorf(px);
        float fy = py - y0f,   fx = px - x0f;
        int y0 = (int)y0f, x0 = (int)x0f;
        float wy0 = 1.f - fy, wx0 = 1.f - fx;
        int base = b*HW;
        #pragma unroll
        for (int ti = 0; ti < 4; ti++) {
            int yi = y0 + (ti >> 1);
            int xi = x0 + (ti & 1);
            float wv = ((ti >> 1) ? fy : wy0) * ((ti & 1) ? fx : wx0);
            bool valid = (yi >= 0 && yi < HH && xi >= 0 && xi < WW);
            int yc = min(max(yi, 0), HH-1);
            int xc = min(max(xi, 0), WW-1);
            tw  [it*4 + ti] = valid ? wv : 0.f;
            tidx[it*4 + ti] = (base + yc*WW + xc) * CH;
        }
    }
    __syncthreads();

    float acc[8][8];
    #pragma unroll
    for (int i = 0; i < 8; i++)
        #pragma unroll
        for (int j = 0; j < 8; j++) acc[i][j] = 0.f;

    int cc  = t & 31;
    int grp = t >> 5;            // 0..7
    int tm  = grp;               // row group (positions)
    int tn  = cc;                // col group (outputs)

    float4*       Bsh4 = (float4*)Bsh;
    const float4* wr4  = (const float4*)wr;

    int br = t >> 3, bq = t & 7;       // B-load mapping: 32 rows x 8 thr/row

    for (int kc = 0; kc < 72; kc++) {
        int k  = kc >> 3;
        int c0 = (kc & 7) << 5;
        int jbase = k*CH + c0;

        // B chunk: 32 rows x 256 floats = 64 float4/row; 8 thr/row x 8 f4 each
        #pragma unroll
        for (int ii = 0; ii < 8; ii++)
            Bsh4[br*64 + bq + ii*8] = wr4[(jbase + br)*64 + bq + ii*8];

        // A chunk: sample 64 pos x 32 channels via precomputed taps
        #pragma unroll
        for (int i = 0; i < 8; i++) {
            int pp = grp*8 + i;
            int tb = (pp*9 + k)*4;
            int c  = c0 + cc;
            float v = tw[tb  ] * xin[tidx[tb  ] + c]
                    + tw[tb+1] * xin[tidx[tb+1] + c]
                    + tw[tb+2] * xin[tidx[tb+2] + c]
                    + tw[tb+3] * xin[tidx[tb+3] + c];
            Ash[cc*65 + pp] = v;
        }
        __syncthreads();

        #pragma unroll
        for (int kk2 = 0; kk2 < 32; kk2++) {
            float a[8];
            #pragma unroll
            for (int i = 0; i < 8; i++) a[i] = Ash[kk2*65 + tm*8 + i];
            float4 b0 = Bsh4[kk2*64 + tn*2];
            float4 b1 = Bsh4[kk2*64 + tn*2 + 1];
            #pragma unroll
            for (int i = 0; i < 8; i++) {
                acc[i][0] += a[i]*b0.x;
                acc[i][1] += a[i]*b0.y;
                acc[i][2] += a[i]*b0.z;
                acc[i][3] += a[i]*b0.w;
                acc[i][4] += a[i]*b1.x;
                acc[i][5] += a[i]*b1.y;
                acc[i][6] += a[i]*b1.z;
                acc[i][7] += a[i]*b1.w;
            }
        }
        __syncthreads();
    }

    // ---- epilogue: bias + relu, NHWC store ----
    float bb[8];
    #pragma unroll
    for (int j = 0; j < 8; j++) bb[j] = bias[tn*8 + j];
    #pragma unroll
    for (int i = 0; i < 8; i++) {
        int gp = pos0 + tm*8 + i;
        float4 o0, o1;
        o0.x = fmaxf(acc[i][0] + bb[0], 0.f);
        o0.y = fmaxf(acc[i][1] + bb[1], 0.f);
        o0.z = fmaxf(acc[i][2] + bb[2], 0.f);
        o0.w = fmaxf(acc[i][3] + bb[3], 0.f);
        o1.x = fmaxf(acc[i][4] + bb[4], 0.f);
        o1.y = fmaxf(acc[i][5] + bb[5], 0.f);
        o1.z = fmaxf(acc[i][6] + bb[6], 0.f);
        o1.w = fmaxf(acc[i][7] + bb[7], 0.f);
        float4* dst = (float4*)(yout + gp*256 + tn*8);
        dst[0] = o0;
        dst[1] = o1;
    }
}

// ---------------- launch ----------------
extern "C" void kernel_launch(void* const* d_in, const int* in_sizes, int n_in,
                              void* d_out, int out_size) {
    const float* x     = (const float*)d_in[0];
    const float* off_w = (const float*)d_in[1];
    const float* off_b = (const float*)d_in[2];
    const float* dw    = (const float*)d_in[3];
    const float* db    = (const float*)d_in[4];
    float* out = (float*)d_out;

    cudaFuncSetAttribute(k_deform, cudaFuncAttributeMaxDynamicSharedMemorySize, DSM_BYTES);

    k_nchw2nhwc<<<(NPOS*CH + 255)/256, 256>>>(x);
    k_wtrans_dw<<<(LAYERS*KDIM*CH + 255)/256, 256>>>(dw);
    k_wtrans_ow<<<(LAYERS*KDIM*18 + 255)/256, 256>>>(off_w);

    dim3 og(NPOS/64, KSPLIT);
    for (int l = 0; l < LAYERS; l++) {
        int flag = l & 1;   // 0: in=g_x0 out=g_x1
        k_offconv<<<og, 256>>>(flag, l, off_b);
        k_deform <<<NPOS/64, 256, DSM_BYTES>>>(flag, l, db);
    }
    // after 4 layers result is in g_x0
    k_nhwc2nchw<<<(NPOS*CH + 255)/256, 256>>>(out);
}